// round 9
// baseline (speedup 1.0000x reference)
#include <cuda_runtime.h>
#include <math.h>

// Problem constants
#define BN 4096      // batch
#define IND 2048     // input dim
#define KC 8192      // codes per split
#define DD 256       // embedding dim per split
#define SS 8         // splits
#define SD 2048      // SS*DD

#define KSPLIT 4
#define KRANGE (KC / KSPLIT)   // 2048 codes per dist block

#define BROW 264     // padded B-row stride (breaks LDS.128 2-way conflicts)

typedef unsigned long long ull;

// ---------------- scratch (device globals; no allocation allowed) ----------
__device__ float g_z[BN * SD];          // encoder output z  [4096,2048]
__device__ float g_zsq[BN * SS];        // ||z_bs||^2
__device__ float g_esq[SS * KC];        // ||e_sk||^2
__device__ ull   g_best[BN * SS];       // packed (dist_bits<<32)|idx, atomicMin
__device__ int   g_counts[SS * KC];     // histogram
__device__ float g_perp[SS];            // per-split perplexity

// ---------------- packed fp32x2 helpers (Blackwell FFMA2) -------------------
__device__ __forceinline__ ull pack_dup(float x) {
    ull r; asm("mov.b64 %0, {%1, %1};" : "=l"(r) : "f"(x)); return r;
}
__device__ __forceinline__ ull pack2(float x, float y) {
    ull r; asm("mov.b64 %0, {%1, %2};" : "=l"(r) : "f"(x), "f"(y)); return r;
}
__device__ __forceinline__ void ffma2(ull& d, ull a, ull b) {
    asm("fma.rn.f32x2 %0, %1, %2, %0;" : "+l"(d) : "l"(a), "l"(b));
}
__device__ __forceinline__ float2 unpack2(ull v) {
    float lo, hi; asm("mov.b64 {%0, %1}, %2;" : "=f"(lo), "=f"(hi) : "l"(v));
    return make_float2(lo, hi);
}

// ---------------- init (graph-replayed each launch) -------------------------
__global__ void init_kernel() {
    int i = blockIdx.x * blockDim.x + threadIdx.x;
    if (i < SS * KC) g_counts[i] = 0;
    if (i < BN * SS) g_best[i] = 0xFFFFFFFFFFFFFFFFull;
}

// ---------------- SGEMM (FFMA2): C[m,n] = sum_k A[m,k]*B[n,k] + bias[n] -----
// Tile 128M x 256N, 256 threads. ty=warp (16 rows/thread, broadcast LDS),
// tx=lane (8 cols/thread as 4 float2 pairs). 64 FFMA2/thread/kstep.
__global__ __launch_bounds__(256) void sgemm_tn2(const float* __restrict__ A,
                                                 const float* __restrict__ Bm,
                                                 const float* __restrict__ bias,
                                                 float* __restrict__ C,
                                                 int N, int Kd) {
    __shared__ float As[128 * 8];     // row-major [row][k]
    __shared__ float Bs[8 * BROW];    // [k][n], padded rows
    const int bm = blockIdx.y * 128;
    const int bn = blockIdx.x * 256;
    const int tid = threadIdx.x;
    const int ty = tid >> 5;         // warp 0..7 -> 16 M rows each
    const int tx = tid & 31;         // lane -> 8 N cols

    const float* Aptr = A + (size_t)(bm + (tid >> 1)) * Kd + ((tid & 1) << 2);
    const float* Bptr = Bm + (size_t)(bn + tid) * Kd;

    ull acc[16][4];
#pragma unroll
    for (int i = 0; i < 16; i++)
#pragma unroll
        for (int j = 0; j < 4; j++) acc[i][j] = 0ull;

    for (int k0 = 0; k0 < Kd; k0 += 8) {
        float4 a4  = *(const float4*)(Aptr + k0);
        float4 b0v = *(const float4*)(Bptr + k0);
        float4 b1v = *(const float4*)(Bptr + k0 + 4);
        __syncthreads();
        *(float4*)&As[(tid >> 1) * 8 + ((tid & 1) << 2)] = a4;
        Bs[0 * BROW + tid] = b0v.x; Bs[1 * BROW + tid] = b0v.y;
        Bs[2 * BROW + tid] = b0v.z; Bs[3 * BROW + tid] = b0v.w;
        Bs[4 * BROW + tid] = b1v.x; Bs[5 * BROW + tid] = b1v.y;
        Bs[6 * BROW + tid] = b1v.z; Bs[7 * BROW + tid] = b1v.w;
        __syncthreads();
#pragma unroll
        for (int kk = 0; kk < 8; kk++) {
            ull b2[4];
            const float* Brow = &Bs[kk * BROW + tx * 8];
            float4 q0 = *(const float4*)Brow;
            float4 q1 = *(const float4*)(Brow + 4);
            b2[0] = pack2(q0.x, q0.y); b2[1] = pack2(q0.z, q0.w);
            b2[2] = pack2(q1.x, q1.y); b2[3] = pack2(q1.z, q1.w);
            const float* Acol = &As[(ty * 16) * 8 + kk];
#pragma unroll
            for (int i = 0; i < 16; i++) {
                ull ad = pack_dup(Acol[i * 8]);
                ffma2(acc[i][0], ad, b2[0]);
                ffma2(acc[i][1], ad, b2[1]);
                ffma2(acc[i][2], ad, b2[2]);
                ffma2(acc[i][3], ad, b2[3]);
            }
        }
    }
#pragma unroll
    for (int i = 0; i < 16; i++) {
        int r = bm + ty * 16 + i;
#pragma unroll
        for (int j = 0; j < 4; j++) {
            int c = bn + tx * 8 + j * 2;
            float2 v = unpack2(acc[i][j]);
            float2 o; o.x = v.x + bias[c]; o.y = v.y + bias[c + 1];
            *(float2*)&C[(size_t)r * N + c] = o;
        }
    }
}

// ---------------- row-wise sum of squares over contiguous 256-chunks --------
__global__ void rowsumsq_kernel(const float* __restrict__ src,
                                float* __restrict__ dst, int nrows) {
    int warp = (blockIdx.x * blockDim.x + threadIdx.x) >> 5;
    int lane = threadIdx.x & 31;
    if (warp >= nrows) return;
    const float* p = src + (size_t)warp * DD;
    float s = 0.0f;
#pragma unroll
    for (int i = 0; i < DD / 32; i++) {
        float v = p[lane + i * 32];
        s += v * v;
    }
#pragma unroll
    for (int o = 16; o; o >>= 1) s += __shfl_xor_sync(0xFFFFFFFFu, s, o);
    if (lane == 0) dst[warp] = s;
}

// ---------------- fused distance + argmin (FFMA2, split-K) ------------------
// grid = (B/128, S, KSPLIT). Block: 128 batch rows x 2048 codes, chunks of 256.
// distance = fl( fl(z_sq + e_sq) - fl(2*cross) ) -- same order as reference.
// Global lexicographic argmin via atomicMin on (dist_bits<<32)|idx.
__global__ __launch_bounds__(256) void dist_argmin2(const float* __restrict__ cb) {
    extern __shared__ float dsm[];
    float* Zs  = dsm;                      // [128][256] row-major
    float* Bsp = dsm + 128 * DD;           // [8][BROW]
    float* Es  = Bsp + 8 * BROW;           // [256]
    float* Zq  = Es + 256;                 // [128]

    const int s     = blockIdx.y;
    const int bm    = blockIdx.x * 128;
    const int kbase = blockIdx.z * KRANGE;
    const int tid = threadIdx.x;
    const int ty = tid >> 5;
    const int tx = tid & 31;

    // load Z tile [128 rows x 256 dims] row-major (coalesced, conflict-free)
    for (int idx = tid; idx < 128 * 64; idx += 256) {
        int row = idx >> 6;
        int d4  = (idx & 63) << 2;
        float4 v = *(const float4*)(g_z + (size_t)(bm + row) * SD + s * DD + d4);
        *(float4*)&Zs[row * 256 + d4] = v;
    }
    if (tid < 128) Zq[tid] = g_zsq[(size_t)(bm + tid) * SS + s];

    float bestd[16];
    int   bidx[16];
#pragma unroll
    for (int i = 0; i < 16; i++) { bestd[i] = INFINITY; bidx[i] = 0; }

    for (int c0 = 0; c0 < KRANGE; c0 += 256) {
        const int kg0 = kbase + c0;
        __syncthreads();   // prev epilogue readers of Es done; also first-iter Zs fence
        if (tid < 64) {
            float4 e4 = *(const float4*)(g_esq + (size_t)s * KC + kg0 + (tid << 2));
            *(float4*)&Es[tid * 4] = e4;
        }
        ull acc[16][4];
#pragma unroll
        for (int i = 0; i < 16; i++)
#pragma unroll
            for (int j = 0; j < 4; j++) acc[i][j] = 0ull;

        const float* cbase = cb + ((size_t)(s * KC + kg0 + tid)) * DD;
        for (int d0 = 0; d0 < DD; d0 += 8) {
            float4 b0v = *(const float4*)(cbase + d0);
            float4 b1v = *(const float4*)(cbase + d0 + 4);
            __syncthreads();
            Bsp[0 * BROW + tid] = b0v.x; Bsp[1 * BROW + tid] = b0v.y;
            Bsp[2 * BROW + tid] = b0v.z; Bsp[3 * BROW + tid] = b0v.w;
            Bsp[4 * BROW + tid] = b1v.x; Bsp[5 * BROW + tid] = b1v.y;
            Bsp[6 * BROW + tid] = b1v.z; Bsp[7 * BROW + tid] = b1v.w;
            __syncthreads();
#pragma unroll
            for (int kk = 0; kk < 8; kk++) {
                ull b2[4];
                const float* Brow = &Bsp[kk * BROW + tx * 8];
                float4 q0 = *(const float4*)Brow;
                float4 q1 = *(const float4*)(Brow + 4);
                b2[0] = pack2(q0.x, q0.y); b2[1] = pack2(q0.z, q0.w);
                b2[2] = pack2(q1.x, q1.y); b2[3] = pack2(q1.z, q1.w);
                const float* Zcol = &Zs[(ty * 16) * 256 + d0 + kk];
#pragma unroll
                for (int i = 0; i < 16; i++) {
                    ull ad = pack_dup(Zcol[i * 256]);
                    ffma2(acc[i][0], ad, b2[0]);
                    ffma2(acc[i][1], ad, b2[1]);
                    ffma2(acc[i][2], ad, b2[2]);
                    ffma2(acc[i][3], ad, b2[3]);
                }
            }
        }
        // epilogue: distances + running argmin (same fp expression as R1)
#pragma unroll
        for (int i = 0; i < 16; i++) {
            float zv = Zq[ty * 16 + i];
#pragma unroll
            for (int j = 0; j < 4; j++) {
                int cl = tx * 8 + j * 2;
                float2 v = unpack2(acc[i][j]);
                float t0 = zv + Es[cl];
                float t1 = zv + Es[cl + 1];
                float dv0 = t0 - 2.0f * v.x;
                float dv1 = t1 - 2.0f * v.y;
                int kg = kg0 + cl;
                if (dv0 < bestd[i] || (dv0 == bestd[i] && kg < bidx[i])) {
                    bestd[i] = dv0; bidx[i] = kg;
                }
                if (dv1 < bestd[i] || (dv1 == bestd[i] && kg + 1 < bidx[i])) {
                    bestd[i] = dv1; bidx[i] = kg + 1;
                }
            }
        }
    }

    // warp-level lexicographic reduction, then global atomicMin on packed key
#pragma unroll
    for (int i = 0; i < 16; i++) {
        float bd = bestd[i]; int bi = bidx[i];
#pragma unroll
        for (int o = 16; o; o >>= 1) {
            float od = __shfl_xor_sync(0xFFFFFFFFu, bd, o);
            int   oi = __shfl_xor_sync(0xFFFFFFFFu, bi, o);
            if (od < bd || (od == bd && oi < bi)) { bd = od; bi = oi; }
        }
        if (tx == 0) {
            ull key = ((ull)__float_as_uint(bd) << 32) | (unsigned)bi;
            atomicMin(&g_best[(size_t)(bm + ty * 16 + i) * SS + s], key);
        }
    }
}

// ---------------- gather quantized + codes + histogram ----------------------
__global__ void gather_pack_kernel(const float* __restrict__ cb,
                                   float* __restrict__ outq,
                                   float* __restrict__ outc) {
    int b = blockIdx.x;
    int g = threadIdx.x >> 5;       // split
    int lane = threadIdx.x & 31;
    int code = (int)(g_best[b * SS + g] & 0xFFFFFFFFull);
    const float4* src = (const float4*)(cb + ((size_t)(g * KC + code)) * DD);
    float4* dst = (float4*)(outq + (size_t)b * SD + g * DD);
    dst[lane] = src[lane];
    dst[lane + 32] = src[lane + 32];
    if (lane == 0) {
        outc[b * SS + g] = (float)code;
        atomicAdd(&g_counts[g * KC + code], 1);
    }
}

// ---------------- perplexity ------------------------------------------------
__global__ void perp_split_kernel() {
    int s = blockIdx.x;
    int tid = threadIdx.x;  // 256
    float sum = 0.0f;
    for (int k = tid; k < KC; k += 256) {
        float p = (float)g_counts[s * KC + k] * (1.0f / (float)BN);
        sum += p * logf(p + 1e-10f);
    }
#pragma unroll
    for (int o = 16; o; o >>= 1) sum += __shfl_xor_sync(0xFFFFFFFFu, sum, o);
    __shared__ float red[8];
    if ((tid & 31) == 0) red[tid >> 5] = sum;
    __syncthreads();
    if (tid == 0) {
        float t = 0.0f;
#pragma unroll
        for (int w = 0; w < 8; w++) t += red[w];
        g_perp[s] = expf(-t);
    }
}

__global__ void finalize_kernel(float* __restrict__ out_perp) {
    float t = 0.0f;
#pragma unroll
    for (int s = 0; s < SS; s++) t += g_perp[s];
    out_perp[0] = t / (float)SS;
}

// ---------------- launch ----------------------------------------------------
extern "C" void kernel_launch(void* const* d_in, const int* in_sizes, int n_in,
                              void* d_out, int out_size) {
    (void)in_sizes; (void)n_in; (void)out_size;
    const float* x     = (const float*)d_in[0];
    const float* enc_w = (const float*)d_in[1];
    const float* enc_b = (const float*)d_in[2];
    const float* cb    = (const float*)d_in[3];
    const float* dec_w = (const float*)d_in[4];
    const float* dec_b = (const float*)d_in[5];

    float* out = (float*)d_out;
    float* out_recon = out;                                  // [4096,2048]
    float* out_quant = out + (size_t)BN * SD;                // [4096,2048]
    float* out_codes = out + (size_t)2 * BN * SD;            // [4096,8]
    float* out_perp  = out_codes + (size_t)BN * SS;          // [1]

    void *pz, *pzsq, *pesq;
    cudaGetSymbolAddress(&pz, g_z);
    cudaGetSymbolAddress(&pzsq, g_zsq);
    cudaGetSymbolAddress(&pesq, g_esq);

    // dynamic smem for dist kernel: Zs + Bsp + Es + Zq
    const int DSM = (128 * DD + 8 * BROW + 256 + 128) * (int)sizeof(float);
    cudaFuncSetAttribute(dist_argmin2,
                         cudaFuncAttributeMaxDynamicSharedMemorySize, DSM);

    init_kernel<<<64, 1024>>>();

    // z = x @ enc_w^T + enc_b
    sgemm_tn2<<<dim3(SD / 256, BN / 128), 256>>>(x, enc_w, enc_b, (float*)pz,
                                                 SD, IND);
    // per-(b,s) ||z||^2 and per-(s,k) ||e||^2
    rowsumsq_kernel<<<(BN * SS) / 8, 256>>>((const float*)pz, (float*)pzsq, BN * SS);
    rowsumsq_kernel<<<(SS * KC) / 8, 256>>>(cb, (float*)pesq, SS * KC);

    // fused distances + argmin (split-K, global atomicMin merge)
    dist_argmin2<<<dim3(BN / 128, SS, KSPLIT), 256, DSM>>>(cb);

    // gather quantized + codes + histogram
    gather_pack_kernel<<<BN, 256>>>(cb, out_quant, out_codes);

    // x_recon = quantized @ dec_w^T + dec_b
    sgemm_tn2<<<dim3(IND / 256, BN / 128), 256>>>(out_quant, dec_w, dec_b,
                                                  out_recon, IND, SD);

    perp_split_kernel<<<SS, 256>>>();
    finalize_kernel<<<1, 1>>>(out_perp);
}